// round 3
// baseline (speedup 1.0000x reference)
#include <cuda_runtime.h>
#include <cstdint>

#define B_ 8
#define T_ 2048
#define H_ 64
#define M_ 32
#define S_ 20
#define E_ 3
#define IN_ 32
#define EPS_ 1e-8f
#define LOG2E_ 1.4426950408889634f

// ---------------- scratch (no cudaMalloc allowed) ----------------
__device__ __align__(16) float g_mhat[B_ * T_ * M_];      // normalized memories
__device__ __align__(16) float g_Q[E_ * B_ * T_ * M_];
__device__ __align__(16) float g_K[E_ * B_ * T_ * M_];
__device__ __align__(16) float g_V[E_ * B_ * T_ * M_];

// ---------------- packed f32x2 helpers (sm_103a) ----------------
static __device__ __forceinline__ unsigned long long pk2(float a, float b) {
    unsigned long long r;
    asm("mov.b64 %0, {%1, %2};" : "=l"(r) : "r"(__float_as_uint(a)), "r"(__float_as_uint(b)));
    return r;
}
static __device__ __forceinline__ void upk2(unsigned long long v, float& a, float& b) {
    unsigned lo, hi;
    asm("mov.b64 {%0, %1}, %2;" : "=r"(lo), "=r"(hi) : "l"(v));
    a = __uint_as_float(lo); b = __uint_as_float(hi);
}
static __device__ __forceinline__ unsigned long long ffma2(
        unsigned long long a, unsigned long long b, unsigned long long c) {
    unsigned long long d;
    asm("fma.rn.f32x2 %0, %1, %2, %3;" : "=l"(d) : "l"(a), "l"(b), "l"(c));
    return d;
}
static __device__ __forceinline__ unsigned long long fmul2(
        unsigned long long a, unsigned long long b) {
    unsigned long long d;
    asm("mul.rn.f32x2 %0, %1, %2;" : "=l"(d) : "l"(a), "l"(b));
    return d;
}

// ---------------- kernel A: memories -> g_mhat ----------------
__global__ __launch_bounds__(256) void mem_kernel(
        const float* __restrict__ x,
        const float* __restrict__ memory,
        const float* __restrict__ iq) {
    __shared__ float iqT[IN_ * M_];   // transposed: iqT[m*IN_+i] = iq[i*M_+m]
    __shared__ float sm[S_ * M_];
    int tid = threadIdx.x;
    for (int n = tid; n < IN_ * M_; n += blockDim.x) {
        int i = n / M_, m = n % M_;
        iqT[m * IN_ + i] = iq[n];
    }
    for (int n = tid; n < S_ * M_; n += blockDim.x) sm[n] = memory[n];
    __syncthreads();

    int bt = blockIdx.x * blockDim.x + tid;   // covers B*T
    float xr[IN_];
    const float4* x4 = (const float4*)(x + (size_t)bt * IN_);
#pragma unroll
    for (int i = 0; i < IN_ / 4; i++) {
        float4 v = x4[i];
        xr[4 * i] = v.x; xr[4 * i + 1] = v.y; xr[4 * i + 2] = v.z; xr[4 * i + 3] = v.w;
    }
    float qv[M_];
#pragma unroll
    for (int m = 0; m < M_; m++) {
        float s = 0.f;
#pragma unroll
        for (int i = 0; i < IN_; i++) s += xr[i] * iqT[m * IN_ + i];
        qv[m] = s;
    }
    // pass 1: row max
    float mx = -3e38f;
    for (int s = 0; s < S_; s++) {
        float d = 0.f;
#pragma unroll
        for (int m = 0; m < M_; m++) d += qv[m] * sm[s * M_ + m];
        mx = fmaxf(mx, d);
    }
    // pass 2: exp, weighted sum
    float L = 0.f;
    float macc[M_];
#pragma unroll
    for (int m = 0; m < M_; m++) macc[m] = 0.f;
    for (int s = 0; s < S_; s++) {
        float d = 0.f;
#pragma unroll
        for (int m = 0; m < M_; m++) d += qv[m] * sm[s * M_ + m];
        float p = exp2f((d - mx) * LOG2E_);
        L += p;
#pragma unroll
        for (int m = 0; m < M_; m++) macc[m] += p * sm[s * M_ + m];
    }
    float invL = 1.0f / L;
    float ss = 0.f;
#pragma unroll
    for (int m = 0; m < M_; m++) {
        float mv = macc[m] * invL;
        macc[m] = mv;
        ss += mv * mv;
    }
    float rinv = 1.0f / fmaxf(sqrtf(ss), EPS_);
    float4* o4 = (float4*)(g_mhat + (size_t)bt * M_);
#pragma unroll
    for (int i = 0; i < M_ / 4; i++) {
        float4 v;
        v.x = macc[4 * i] * rinv; v.y = macc[4 * i + 1] * rinv;
        v.z = macc[4 * i + 2] * rinv; v.w = macc[4 * i + 3] * rinv;
        o4[i] = v;
    }
}

// ---------------- kernel B: QKV projection ----------------
__global__ __launch_bounds__(128) void qkv_kernel(
        const float* __restrict__ hidden,
        const float* __restrict__ Wq,
        const float* __restrict__ Wk,
        const float* __restrict__ Wv) {
    __shared__ float w[3][H_ * M_];
    int e = blockIdx.z, b = blockIdx.y;
    int tid = threadIdx.x;
    const float* Ws[3] = {Wq, Wk, Wv};
    for (int p = 0; p < 3; p++)
        for (int n = tid; n < H_ * M_; n += blockDim.x)
            w[p][n] = Ws[p][e * H_ * M_ + n];
    __syncthreads();

    int t = blockIdx.x * blockDim.x + tid;
    size_t row = (size_t)(e * B_ + b) * T_ + t;
    float h[H_];
    const float4* h4 = (const float4*)(hidden + row * H_);
#pragma unroll
    for (int i = 0; i < H_ / 4; i++) {
        float4 v = h4[i];
        h[4 * i] = v.x; h[4 * i + 1] = v.y; h[4 * i + 2] = v.z; h[4 * i + 3] = v.w;
    }
    float* outs[3] = {g_Q, g_K, g_V};
    for (int p = 0; p < 3; p++) {
        float acc[M_];
#pragma unroll
        for (int m = 0; m < M_; m++) acc[m] = 0.f;
        for (int i = 0; i < H_; i++) {
            float hv = h[i];
#pragma unroll
            for (int m = 0; m < M_; m++) acc[m] += hv * w[p][i * M_ + m];
        }
        float4* o4 = (float4*)(outs[p] + row * M_);
#pragma unroll
        for (int i = 0; i < M_ / 4; i++) {
            float4 v;
            v.x = acc[4 * i]; v.y = acc[4 * i + 1]; v.z = acc[4 * i + 2]; v.w = acc[4 * i + 3];
            o4[i] = v;
        }
    }
}

// ---------------- kernel C: flash attention + fused cosine ----------------
#define BR_ 256
#define BC_ 64

__global__ __launch_bounds__(256) void attn_kernel(float* __restrict__ out) {
    __shared__ __align__(16) float Ks[BC_ * M_];
    __shared__ __align__(16) float Vs[BC_ * M_];
    int e = blockIdx.z, b = blockIdx.y;
    int tid = threadIdx.x;
    int t = blockIdx.x * BR_ + tid;
    size_t ebbase = (size_t)(e * B_ + b) * T_ * M_;

    // q row -> packed registers
    unsigned long long qp[16];
    const ulonglong2* q2 = (const ulonglong2*)(g_Q + ebbase + (size_t)t * M_);
#pragma unroll
    for (int i = 0; i < 8; i++) {
        ulonglong2 v = q2[i];
        qp[2 * i] = v.x; qp[2 * i + 1] = v.y;
    }
    unsigned long long acc[16];
#pragma unroll
    for (int i = 0; i < 16; i++) acc[i] = 0ull;   // bit pattern (0.f, 0.f)
    float m = -3e38f, l = 0.f;

    const float4* kg = (const float4*)(g_K + ebbase);
    const float4* vg = (const float4*)(g_V + ebbase);

    for (int kt = 0; kt < T_ / BC_; kt++) {
        // cooperative tile load: 512 float4 per matrix, 2 per thread
#pragma unroll
        for (int r = 0; r < 2; r++) {
            int idx = r * 256 + tid;
            ((float4*)Ks)[idx] = kg[kt * (BC_ * M_ / 4) + idx];
            ((float4*)Vs)[idx] = vg[kt * (BC_ * M_ / 4) + idx];
        }
        __syncthreads();

        for (int j = 0; j < BC_; j++) {
            // score = q . K[j]   (broadcast smem reads, packed fma)
            const ulonglong2* kr = (const ulonglong2*)(Ks + j * M_);
            unsigned long long s0 = 0ull, s1 = 0ull;
#pragma unroll
            for (int i = 0; i < 8; i++) {
                ulonglong2 kk = kr[i];
                s0 = ffma2(qp[2 * i], kk.x, s0);
                s1 = ffma2(qp[2 * i + 1], kk.y, s1);
            }
            float a0, a1, b0, b1;
            upk2(s0, a0, a1); upk2(s1, b0, b1);
            float s = (a0 + b0) + (a1 + b1);

            if (s > m) {   // rare (~8 times per 2048 keys)
                float sc = exp2f((m - s) * LOG2E_);
                unsigned long long sc2 = pk2(sc, sc);
                l *= sc;
#pragma unroll
                for (int i = 0; i < 16; i++) acc[i] = fmul2(acc[i], sc2);
                m = s;
            }
            float p = exp2f((s - m) * LOG2E_);
            l += p;
            unsigned long long p2 = pk2(p, p);
            const ulonglong2* vr = (const ulonglong2*)(Vs + j * M_);
#pragma unroll
            for (int i = 0; i < 8; i++) {
                ulonglong2 vv = vr[i];
                acc[2 * i]     = ffma2(p2, vv.x, acc[2 * i]);
                acc[2 * i + 1] = ffma2(p2, vv.y, acc[2 * i + 1]);
            }
        }
        __syncthreads();
    }

    // epilogue: out_row = acc / l ; cos(out_row, mhat)
    float o[M_];
#pragma unroll
    for (int i = 0; i < 16; i++) upk2(acc[i], o[2 * i], o[2 * i + 1]);
    float invl = 1.0f / l;
    float n2 = 0.f;
#pragma unroll
    for (int mm = 0; mm < M_; mm++) {
        o[mm] *= invl;
        n2 += o[mm] * o[mm];
    }
    const float* mh = g_mhat + ((size_t)b * T_ + t) * M_;
    float d = 0.f;
#pragma unroll
    for (int mm = 0; mm < M_; mm++) d += o[mm] * mh[mm];
    float cosv = d / fmaxf(sqrtf(n2), EPS_);
    out[((size_t)b * T_ + t) * E_ + e] = cosv;
}

// ---------------- launch ----------------
extern "C" void kernel_launch(void* const* d_in, const int* in_sizes, int n_in,
                              void* d_out, int out_size) {
    const float* x      = (const float*)d_in[0];
    const float* hidden = (const float*)d_in[1];
    const float* memory = (const float*)d_in[2];
    const float* Wq     = (const float*)d_in[3];
    const float* Wk     = (const float*)d_in[4];
    const float* Wv     = (const float*)d_in[5];
    const float* iq     = (const float*)d_in[6];
    float* out = (float*)d_out;

    mem_kernel<<<(B_ * T_) / 256, 256>>>(x, memory, iq);
    qkv_kernel<<<dim3(T_ / 128, B_, E_), 128>>>(hidden, Wq, Wk, Wv);
    attn_kernel<<<dim3(T_ / BR_, B_, E_), 256>>>(out);
}

// round 4
// speedup vs baseline: 1.1044x; 1.1044x over previous
#include <cuda_runtime.h>
#include <cstdint>

#define B_ 8
#define T_ 2048
#define H_ 64
#define M_ 32
#define S_ 20
#define E_ 3
#define IN_ 32
#define EPS_ 1e-8f
#define LOG2E_ 1.4426950408889634f

// ---------------- scratch (no cudaMalloc allowed) ----------------
__device__ __align__(16) float g_mhat[B_ * T_ * M_];      // normalized memories
__device__ __align__(16) float g_Q[E_ * B_ * T_ * M_];
__device__ __align__(16) float g_K[E_ * B_ * T_ * M_];
__device__ __align__(16) float g_V[E_ * B_ * T_ * M_];

// ---------------- packed f32x2 helpers (sm_103a) ----------------
static __device__ __forceinline__ unsigned long long pk2(float a, float b) {
    unsigned long long r;
    asm("mov.b64 %0, {%1, %2};" : "=l"(r) : "r"(__float_as_uint(a)), "r"(__float_as_uint(b)));
    return r;
}
static __device__ __forceinline__ void upk2(unsigned long long v, float& a, float& b) {
    unsigned lo, hi;
    asm("mov.b64 {%0, %1}, %2;" : "=r"(lo), "=r"(hi) : "l"(v));
    a = __uint_as_float(lo); b = __uint_as_float(hi);
}
static __device__ __forceinline__ unsigned long long ffma2(
        unsigned long long a, unsigned long long b, unsigned long long c) {
    unsigned long long d;
    asm("fma.rn.f32x2 %0, %1, %2, %3;" : "=l"(d) : "l"(a), "l"(b), "l"(c));
    return d;
}
static __device__ __forceinline__ unsigned long long fadd2(
        unsigned long long a, unsigned long long b) {
    unsigned long long d;
    asm("add.rn.f32x2 %0, %1, %2;" : "=l"(d) : "l"(a), "l"(b));
    return d;
}
static __device__ __forceinline__ unsigned long long fmul2(
        unsigned long long a, unsigned long long b) {
    unsigned long long d;
    asm("mul.rn.f32x2 %0, %1, %2;" : "=l"(d) : "l"(a), "l"(b));
    return d;
}
// guaranteed-MUFU exp2
static __device__ __forceinline__ float ex2f(float x) {
    float r;
    asm("ex2.approx.ftz.f32 %0, %1;" : "=f"(r) : "f"(x));
    return r;
}

// ---------------- kernel A: memories -> g_mhat ----------------
__global__ __launch_bounds__(256) void mem_kernel(
        const float* __restrict__ x,
        const float* __restrict__ memory,
        const float* __restrict__ iq) {
    __shared__ float iqT[IN_ * M_];   // transposed: iqT[m*IN_+i] = iq[i*M_+m]
    __shared__ float sm[S_ * M_];
    int tid = threadIdx.x;
    for (int n = tid; n < IN_ * M_; n += blockDim.x) {
        int i = n / M_, m = n % M_;
        iqT[m * IN_ + i] = iq[n];
    }
    for (int n = tid; n < S_ * M_; n += blockDim.x) sm[n] = memory[n];
    __syncthreads();

    int bt = blockIdx.x * blockDim.x + tid;   // covers B*T
    float xr[IN_];
    const float4* x4 = (const float4*)(x + (size_t)bt * IN_);
#pragma unroll
    for (int i = 0; i < IN_ / 4; i++) {
        float4 v = x4[i];
        xr[4 * i] = v.x; xr[4 * i + 1] = v.y; xr[4 * i + 2] = v.z; xr[4 * i + 3] = v.w;
    }
    float qv[M_];
#pragma unroll
    for (int m = 0; m < M_; m++) {
        float s = 0.f;
#pragma unroll
        for (int i = 0; i < IN_; i++) s += xr[i] * iqT[m * IN_ + i];
        qv[m] = s;
    }
    float mx = -3e38f;
    for (int s = 0; s < S_; s++) {
        float d = 0.f;
#pragma unroll
        for (int m = 0; m < M_; m++) d += qv[m] * sm[s * M_ + m];
        mx = fmaxf(mx, d);
    }
    float L = 0.f;
    float macc[M_];
#pragma unroll
    for (int m = 0; m < M_; m++) macc[m] = 0.f;
    for (int s = 0; s < S_; s++) {
        float d = 0.f;
#pragma unroll
        for (int m = 0; m < M_; m++) d += qv[m] * sm[s * M_ + m];
        float p = ex2f((d - mx) * LOG2E_);
        L += p;
#pragma unroll
        for (int m = 0; m < M_; m++) macc[m] += p * sm[s * M_ + m];
    }
    float invL = 1.0f / L;
    float ss = 0.f;
#pragma unroll
    for (int m = 0; m < M_; m++) {
        float mv = macc[m] * invL;
        macc[m] = mv;
        ss += mv * mv;
    }
    float rinv = 1.0f / fmaxf(sqrtf(ss), EPS_);
    float4* o4 = (float4*)(g_mhat + (size_t)bt * M_);
#pragma unroll
    for (int i = 0; i < M_ / 4; i++) {
        float4 v;
        v.x = macc[4 * i] * rinv; v.y = macc[4 * i + 1] * rinv;
        v.z = macc[4 * i + 2] * rinv; v.w = macc[4 * i + 3] * rinv;
        o4[i] = v;
    }
}

// ---------------- kernel B: QKV projection ----------------
__global__ __launch_bounds__(128) void qkv_kernel(
        const float* __restrict__ hidden,
        const float* __restrict__ Wq,
        const float* __restrict__ Wk,
        const float* __restrict__ Wv) {
    __shared__ float w[3][H_ * M_];
    int e = blockIdx.z, b = blockIdx.y;
    int tid = threadIdx.x;
    const float* Ws[3] = {Wq, Wk, Wv};
    for (int p = 0; p < 3; p++)
        for (int n = tid; n < H_ * M_; n += blockDim.x)
            w[p][n] = Ws[p][e * H_ * M_ + n];
    __syncthreads();

    int t = blockIdx.x * blockDim.x + tid;
    size_t row = (size_t)(e * B_ + b) * T_ + t;
    float h[H_];
    const float4* h4 = (const float4*)(hidden + row * H_);
#pragma unroll
    for (int i = 0; i < H_ / 4; i++) {
        float4 v = h4[i];
        h[4 * i] = v.x; h[4 * i + 1] = v.y; h[4 * i + 2] = v.z; h[4 * i + 3] = v.w;
    }
    float* outs[3] = {g_Q, g_K, g_V};
    for (int p = 0; p < 3; p++) {
        float acc[M_];
#pragma unroll
        for (int m = 0; m < M_; m++) acc[m] = 0.f;
        for (int i = 0; i < H_; i++) {
            float hv = h[i];
#pragma unroll
            for (int m = 0; m < M_; m++) acc[m] += hv * w[p][i * M_ + m];
        }
        float4* o4 = (float4*)(outs[p] + row * M_);
#pragma unroll
        for (int i = 0; i < M_ / 4; i++) {
            float4 v;
            v.x = acc[4 * i]; v.y = acc[4 * i + 1]; v.z = acc[4 * i + 2]; v.w = acc[4 * i + 3];
            o4[i] = v;
        }
    }
}

// ---------------- kernel C: flash attention + fused cosine ----------------
#define BR_ 256
#define BC_ 128      // keys per smem tile
#define KJ_ 8        // keys per score-stage

__global__ __launch_bounds__(256, 2) void attn_kernel(float* __restrict__ out) {
    __shared__ __align__(16) float Ks[BC_ * M_];
    __shared__ __align__(16) float Vs[BC_ * M_];
    int e = blockIdx.z, b = blockIdx.y;
    int tid = threadIdx.x;
    int t = blockIdx.x * BR_ + tid;
    size_t ebbase = (size_t)(e * B_ + b) * T_ * M_;

    // q row -> packed registers
    unsigned long long qp[16];
    const ulonglong2* q2 = (const ulonglong2*)(g_Q + ebbase + (size_t)t * M_);
#pragma unroll
    for (int i = 0; i < 8; i++) {
        ulonglong2 v = q2[i];
        qp[2 * i] = v.x; qp[2 * i + 1] = v.y;
    }
    unsigned long long acc[16];
#pragma unroll
    for (int i = 0; i < 16; i++) acc[i] = 0ull;
    float m = -3e38f, l = 0.f;

    const float4* kg = (const float4*)(g_K + ebbase);
    const float4* vg = (const float4*)(g_V + ebbase);

    for (int kt = 0; kt < T_ / BC_; kt++) {
        // cooperative tile load: BC_*M_/4 = 1024 float4 per matrix, 4 per thread
#pragma unroll
        for (int r = 0; r < BC_ * M_ / 4 / 256; r++) {
            int idx = r * 256 + tid;
            ((float4*)Ks)[idx] = kg[kt * (BC_ * M_ / 4) + idx];
            ((float4*)Vs)[idx] = vg[kt * (BC_ * M_ / 4) + idx];
        }
        __syncthreads();

        for (int j0 = 0; j0 < BC_; j0 += KJ_) {
            // ---- stage 1: 8 scores, 16 independent fma2 chains ----
            float sc[KJ_];
#pragma unroll
            for (int jj = 0; jj < KJ_; jj++) {
                const ulonglong2* kr = (const ulonglong2*)(Ks + (j0 + jj) * M_);
                unsigned long long s0 = 0ull, s1 = 0ull;
#pragma unroll
                for (int i = 0; i < 8; i++) {
                    ulonglong2 kk = kr[i];
                    s0 = ffma2(qp[2 * i], kk.x, s0);
                    s1 = ffma2(qp[2 * i + 1], kk.y, s1);
                }
                s0 = fadd2(s0, s1);
                float a0, a1;
                upk2(s0, a0, a1);
                sc[jj] = (a0 + a1) * LOG2E_;     // log2-domain score
            }
            // ---- stage 2: tile max, rare rescale ----
            float m8 = fmaxf(fmaxf(fmaxf(sc[0], sc[1]), fmaxf(sc[2], sc[3])),
                             fmaxf(fmaxf(sc[4], sc[5]), fmaxf(sc[6], sc[7])));
            if (m8 > m) {
                float s = ex2f(m - m8);
                unsigned long long s2 = pk2(s, s);
                l *= s;
#pragma unroll
                for (int i = 0; i < 16; i++) acc[i] = fmul2(acc[i], s2);
                m = m8;
            }
            // ---- stage 3: exp + PV ----
#pragma unroll
            for (int jj = 0; jj < KJ_; jj++) {
                float p = ex2f(sc[jj] - m);
                l += p;
                unsigned long long p2 = pk2(p, p);
                const ulonglong2* vr = (const ulonglong2*)(Vs + (j0 + jj) * M_);
#pragma unroll
                for (int i = 0; i < 8; i++) {
                    ulonglong2 vv = vr[i];
                    acc[2 * i]     = ffma2(p2, vv.x, acc[2 * i]);
                    acc[2 * i + 1] = ffma2(p2, vv.y, acc[2 * i + 1]);
                }
            }
        }
        __syncthreads();
    }

    // epilogue: out_row = acc / l ; cos(out_row, mhat)
    float o[M_];
#pragma unroll
    for (int i = 0; i < 16; i++) upk2(acc[i], o[2 * i], o[2 * i + 1]);
    float invl = 1.0f / l;
    float n2 = 0.f;
#pragma unroll
    for (int mm = 0; mm < M_; mm++) {
        o[mm] *= invl;
        n2 += o[mm] * o[mm];
    }
    const float* mh = g_mhat + ((size_t)b * T_ + t) * M_;
    float d = 0.f;
#pragma unroll
    for (int mm = 0; mm < M_; mm++) d += o[mm] * mh[mm];
    float cosv = d / fmaxf(sqrtf(n2), EPS_);
    out[((size_t)b * T_ + t) * E_ + e] = cosv;
}

// ---------------- launch ----------------
extern "C" void kernel_launch(void* const* d_in, const int* in_sizes, int n_in,
                              void* d_out, int out_size) {
    const float* x      = (const float*)d_in[0];
    const float* hidden = (const float*)d_in[1];
    const float* memory = (const float*)d_in[2];
    const float* Wq     = (const float*)d_in[3];
    const float* Wk     = (const float*)d_in[4];
    const float* Wv     = (const float*)d_in[5];
    const float* iq     = (const float*)d_in[6];
    float* out = (float*)d_out;

    mem_kernel<<<(B_ * T_) / 256, 256>>>(x, memory, iq);
    qkv_kernel<<<dim3(T_ / 128, B_, E_), 128>>>(hidden, Wq, Wk, Wv);
    attn_kernel<<<dim3(T_ / BR_, B_, E_), 256>>>(out);
}

// round 7
// speedup vs baseline: 3.4235x; 3.0999x over previous
#include <cuda_runtime.h>
#include <cuda_bf16.h>
#include <cstdint>

#define B_ 8
#define T_ 2048
#define H_ 64
#define M_ 32
#define S_ 20
#define E_ 3
#define IN_ 32
#define EPS_ 1e-8f
#define LOG2E_ 1.4426950408889634f

#define TQ_ 128          // q rows per CTA
#define TK_ 64           // keys per smem tile
#define NKT_ (T_ / TK_)  // 32

// ---------------- scratch (no cudaMalloc allowed) ----------------
__device__ __align__(16) float g_mhat[B_ * T_ * M_];
// Q,K rows: [hi 32 bf16 | lo 32 bf16] = 32 uints = 128B per row
__device__ __align__(16) unsigned int g_Qs[E_ * B_ * T_ * 32];
__device__ __align__(16) unsigned int g_Ks[E_ * B_ * T_ * 32];
// V transposed planes: [e][b][m][t/2] bf16 pairs
__device__ __align__(16) unsigned int g_Vthi[E_ * B_ * 32 * (T_ / 2)];
__device__ __align__(16) unsigned int g_Vtlo[E_ * B_ * 32 * (T_ / 2)];

// ---------------- helpers ----------------
static __device__ __forceinline__ float ex2f(float x) {
    float r; asm("ex2.approx.ftz.f32 %0, %1;" : "=f"(r) : "f"(x)); return r;
}
static __device__ __forceinline__ unsigned short f2bf(float f) {
    __nv_bfloat16 h = __float2bfloat16(f);
    return *reinterpret_cast<unsigned short*>(&h);
}
static __device__ __forceinline__ float bf2f(unsigned short u) {
    __nv_bfloat16 h; *reinterpret_cast<unsigned short*>(&h) = u;
    return __bfloat162float(h);
}
// pack {lo16=lo, hi16=hi}
static __device__ __forceinline__ unsigned int pack2(float hi, float lo) {
    unsigned int d;
    asm("cvt.rn.bf16x2.f32 %0, %1, %2;" : "=r"(d) : "f"(hi), "f"(lo));
    return d;
}
static __device__ __forceinline__ float unpk_lo(unsigned int v) {
    return __uint_as_float(v << 16);
}
static __device__ __forceinline__ float unpk_hi(unsigned int v) {
    return __uint_as_float(v & 0xffff0000u);
}
// m16n8k16 row.col f32.bf16.bf16.f32
static __device__ __forceinline__ void mma16816(
        float* c, unsigned int a0, unsigned int a1, unsigned int a2, unsigned int a3,
        unsigned int b0, unsigned int b1) {
    asm volatile(
        "mma.sync.aligned.m16n8k16.row.col.f32.bf16.bf16.f32 "
        "{%0,%1,%2,%3}, {%4,%5,%6,%7}, {%8,%9}, {%0,%1,%2,%3};"
        : "+f"(c[0]), "+f"(c[1]), "+f"(c[2]), "+f"(c[3])
        : "r"(a0), "r"(a1), "r"(a2), "r"(a3), "r"(b0), "r"(b1));
}

// ---------------- kernel A: memories -> g_mhat ----------------
__global__ __launch_bounds__(256) void mem_kernel(
        const float* __restrict__ x,
        const float* __restrict__ memory,
        const float* __restrict__ iq) {
    __shared__ float iqT[IN_ * M_];
    __shared__ float sm[S_ * M_];
    int tid = threadIdx.x;
    for (int n = tid; n < IN_ * M_; n += blockDim.x) {
        int i = n / M_, m = n % M_;
        iqT[m * IN_ + i] = iq[n];
    }
    for (int n = tid; n < S_ * M_; n += blockDim.x) sm[n] = memory[n];
    __syncthreads();

    int bt = blockIdx.x * blockDim.x + tid;
    float xr[IN_];
    const float4* x4 = (const float4*)(x + (size_t)bt * IN_);
#pragma unroll
    for (int i = 0; i < IN_ / 4; i++) {
        float4 v = x4[i];
        xr[4 * i] = v.x; xr[4 * i + 1] = v.y; xr[4 * i + 2] = v.z; xr[4 * i + 3] = v.w;
    }
    float qv[M_];
#pragma unroll
    for (int m = 0; m < M_; m++) {
        float s = 0.f;
#pragma unroll
        for (int i = 0; i < IN_; i++) s += xr[i] * iqT[m * IN_ + i];
        qv[m] = s;
    }
    float mx = -3e38f;
    for (int s = 0; s < S_; s++) {
        float d = 0.f;
#pragma unroll
        for (int m = 0; m < M_; m++) d += qv[m] * sm[s * M_ + m];
        mx = fmaxf(mx, d);
    }
    float L = 0.f;
    float macc[M_];
#pragma unroll
    for (int m = 0; m < M_; m++) macc[m] = 0.f;
    for (int s = 0; s < S_; s++) {
        float d = 0.f;
#pragma unroll
        for (int m = 0; m < M_; m++) d += qv[m] * sm[s * M_ + m];
        float p = ex2f((d - mx) * LOG2E_);
        L += p;
#pragma unroll
        for (int m = 0; m < M_; m++) macc[m] += p * sm[s * M_ + m];
    }
    float invL = 1.0f / L;
    float ss = 0.f;
#pragma unroll
    for (int m = 0; m < M_; m++) {
        float mv = macc[m] * invL;
        macc[m] = mv;
        ss += mv * mv;
    }
    float rinv = 1.0f / fmaxf(sqrtf(ss), EPS_);
    float4* o4 = (float4*)(g_mhat + (size_t)bt * M_);
#pragma unroll
    for (int i = 0; i < M_ / 4; i++) {
        float4 v;
        v.x = macc[4 * i] * rinv; v.y = macc[4 * i + 1] * rinv;
        v.z = macc[4 * i + 2] * rinv; v.w = macc[4 * i + 3] * rinv;
        o4[i] = v;
    }
}

// ---------------- kernel B: QKV projection + split/pack/transpose ----------------
static __device__ __forceinline__ void split_pack_row(const float* a, unsigned int* dst) {
#pragma unroll
    for (int i = 0; i < 16; i++) {
        unsigned short h0 = f2bf(a[2 * i]), h1 = f2bf(a[2 * i + 1]);
        dst[i] = (unsigned)h0 | ((unsigned)h1 << 16);
        float l0 = a[2 * i] - bf2f(h0), l1 = a[2 * i + 1] - bf2f(h1);
        dst[16 + i] = (unsigned)f2bf(l0) | ((unsigned)f2bf(l1) << 16);
    }
}

__global__ __launch_bounds__(128) void qkv_kernel(
        const float* __restrict__ hidden,
        const float* __restrict__ Wq,
        const float* __restrict__ Wk,
        const float* __restrict__ Wv) {
    __shared__ float w[3][H_ * M_];
    __shared__ float sv[128 * 32];
    int e = blockIdx.z, b = blockIdx.y;
    int tid = threadIdx.x;
    const float* Ws[3] = {Wq, Wk, Wv};
    for (int p = 0; p < 3; p++)
        for (int n = tid; n < H_ * M_; n += blockDim.x)
            w[p][n] = Ws[p][e * H_ * M_ + n];
    __syncthreads();

    int t0 = blockIdx.x * 128;
    int t = t0 + tid;
    size_t row = (size_t)(e * B_ + b) * T_ + t;
    float h[H_];
    const float4* h4 = (const float4*)(hidden + row * H_);
#pragma unroll
    for (int i = 0; i < H_ / 4; i++) {
        float4 v = h4[i];
        h[4 * i] = v.x; h[4 * i + 1] = v.y; h[4 * i + 2] = v.z; h[4 * i + 3] = v.w;
    }
    for (int p = 0; p < 3; p++) {
        float acc[M_];
#pragma unroll
        for (int m = 0; m < M_; m++) acc[m] = 0.f;
        for (int i = 0; i < H_; i++) {
            float hv = h[i];
#pragma unroll
            for (int m = 0; m < M_; m++) acc[m] += hv * w[p][i * M_ + m];
        }
        if (p == 0) {
#pragma unroll
            for (int m = 0; m < M_; m++) acc[m] *= LOG2E_;   // log2-domain scores
            unsigned int pk[32];
            split_pack_row(acc, pk);
            uint4* o = (uint4*)(g_Qs + row * 32);
#pragma unroll
            for (int i = 0; i < 8; i++) o[i] = ((uint4*)pk)[i];
        } else if (p == 1) {
            unsigned int pk[32];
            split_pack_row(acc, pk);
            uint4* o = (uint4*)(g_Ks + row * 32);
#pragma unroll
            for (int i = 0; i < 8; i++) o[i] = ((uint4*)pk)[i];
        } else {
#pragma unroll
            for (int m = 0; m < M_; m++) sv[tid * 32 + m] = acc[m];
        }
    }
    __syncthreads();
    // transpose V: thread owns (m, t-chunk of 32)
    int m = tid & 31, tc = tid >> 5;
    size_t vbase = ((size_t)(e * B_ + b) * 32 + m) * (T_ / 2) + (size_t)(t0 + tc * 32) / 2;
#pragma unroll
    for (int j = 0; j < 16; j++) {
        float f0 = sv[(tc * 32 + 2 * j) * 32 + m];
        float f1 = sv[(tc * 32 + 2 * j + 1) * 32 + m];
        unsigned short h0 = f2bf(f0), h1 = f2bf(f1);
        g_Vthi[vbase + j] = (unsigned)h0 | ((unsigned)h1 << 16);
        float l0 = f0 - bf2f(h0), l1 = f1 - bf2f(h1);
        g_Vtlo[vbase + j] = (unsigned)f2bf(l0) | ((unsigned)f2bf(l1) << 16);
    }
}

// ---------------- kernel C: HMMA flash attention + fused cosine ----------------
// smem: Q 128 rows x 128B; K 64 rows x (128+16)B; VT hi/lo 32 rows x (128+16)B
#define KST_ 144
#define VST_ 144

__global__ __launch_bounds__(256, 2) void attn_kernel(float* __restrict__ out) {
    __shared__ __align__(16) char Qsm[TQ_ * 128];
    __shared__ __align__(16) char Ksm[TK_ * KST_];
    __shared__ __align__(16) char Vhism[32 * VST_];
    __shared__ __align__(16) char Vlosm[32 * VST_];

    int tid = threadIdx.x, wid = tid >> 5, lane = tid & 31;
    int e = blockIdx.z, b = blockIdx.y;
    int qbase = blockIdx.x * TQ_;
    size_t eb = (size_t)(e * B_ + b);
    int lq = lane >> 2;      // 0..7
    int lr = lane & 3;       // 0..3

    // ---- load Q tile to smem ----
    {
        const uint4* qg = (const uint4*)g_Qs + (eb * T_ + qbase) * 8;
#pragma unroll
        for (int j = 0; j < 4; j++) {
            int i = tid + j * 256;            // 0..1023
            int r = i >> 3, ch = i & 7;
            *(uint4*)(Qsm + r * 128 + ch * 16) = qg[(size_t)r * 8 + ch];
        }
    }
    __syncthreads();

    // ---- extract persistent Q A-fragments ----
    unsigned int qhi[2][4], qlo[2][4];
    {
        int r0 = wid * 16 + lq;
#pragma unroll
        for (int kc = 0; kc < 2; kc++) {
            int off = (8 * kc + lr) * 4;
            qhi[kc][0] = *(const unsigned int*)(Qsm + r0 * 128 + off);
            qhi[kc][1] = *(const unsigned int*)(Qsm + (r0 + 8) * 128 + off);
            qhi[kc][2] = *(const unsigned int*)(Qsm + r0 * 128 + off + 16);
            qhi[kc][3] = *(const unsigned int*)(Qsm + (r0 + 8) * 128 + off + 16);
            qlo[kc][0] = *(const unsigned int*)(Qsm + r0 * 128 + 64 + off);
            qlo[kc][1] = *(const unsigned int*)(Qsm + (r0 + 8) * 128 + 64 + off);
            qlo[kc][2] = *(const unsigned int*)(Qsm + r0 * 128 + 64 + off + 16);
            qlo[kc][3] = *(const unsigned int*)(Qsm + (r0 + 8) * 128 + 64 + off + 16);
        }
    }

    float o[4][4];
#pragma unroll
    for (int i = 0; i < 4; i++)
#pragma unroll
        for (int j = 0; j < 4; j++) o[i][j] = 0.f;
    float m0 = -1e30f, m1 = -1e30f;

    const uint4* kg = (const uint4*)g_Ks + eb * T_ * 8;
    const uint4* vhg = (const uint4*)g_Vthi + eb * 32 * 256;
    const uint4* vlg = (const uint4*)g_Vtlo + eb * 32 * 256;

    for (int kt = 0; kt < NKT_; kt++) {
        __syncthreads();
        // ---- cooperative tile load: K 512 uint4, Vhi 256, Vlo 256 ----
        {
            int i = tid;                         // K part 1: t = i>>3
            int t = i >> 3, ch = i & 7;
            *(uint4*)(Ksm + t * KST_ + ch * 16) = kg[(size_t)(kt * TK_ + t) * 8 + ch];
            i = tid + 256;
            t = i >> 3; ch = i & 7;
            *(uint4*)(Ksm + t * KST_ + ch * 16) = kg[(size_t)(kt * TK_ + t) * 8 + ch];
            int m = tid >> 3, vch = tid & 7;
            *(uint4*)(Vhism + m * VST_ + vch * 16) = vhg[(size_t)m * 256 + kt * 8 + vch];
            *(uint4*)(Vlosm + m * VST_ + vch * 16) = vlg[(size_t)m * 256 + kt * 8 + vch];
        }
        __syncthreads();

        // ---- S = Q K^T (split bf16, 3 passes), 8 nchunks of 8 keys ----
        float sc[8][4];
#pragma unroll
        for (int n = 0; n < 8; n++) {
            sc[n][0] = sc[n][1] = sc[n][2] = sc[n][3] = 0.f;
            const char* rowp = Ksm + (n * 8 + lq) * KST_;
#pragma unroll
            for (int kc = 0; kc < 2; kc++) {
                int off = 32 * kc + lr * 4;
                unsigned int bh0 = *(const unsigned int*)(rowp + off);
                unsigned int bh1 = *(const unsigned int*)(rowp + off + 16);
                unsigned int bl0 = *(const unsigned int*)(rowp + 64 + off);
                unsigned int bl1 = *(const unsigned int*)(rowp + 64 + off + 16);
                mma16816(sc[n], qhi[kc][0], qhi[kc][1], qhi[kc][2], qhi[kc][3], bh0, bh1);
                mma16816(sc[n], qlo[kc][0], qlo[kc][1], qlo[kc][2], qlo[kc][3], bh0, bh1);
                mma16816(sc[n], qhi[kc][0], qhi[kc][1], qhi[kc][2], qhi[kc][3], bl0, bl1);
            }
        }

        // ---- online max (log2 domain), rescale O ----
        float mt0 = -1e30f, mt1 = -1e30f;
#pragma unroll
        for (int n = 0; n < 8; n++) {
            mt0 = fmaxf(mt0, fmaxf(sc[n][0], sc[n][1]));
            mt1 = fmaxf(mt1, fmaxf(sc[n][2], sc[n][3]));
        }
        mt0 = fmaxf(mt0, __shfl_xor_sync(0xffffffffu, mt0, 1));
        mt0 = fmaxf(mt0, __shfl_xor_sync(0xffffffffu, mt0, 2));
        mt1 = fmaxf(mt1, __shfl_xor_sync(0xffffffffu, mt1, 1));
        mt1 = fmaxf(mt1, __shfl_xor_sync(0xffffffffu, mt1, 2));
        float mn0 = fmaxf(m0, mt0), mn1 = fmaxf(m1, mt1);
        float s0 = ex2f(m0 - mn0), s1 = ex2f(m1 - mn1);
        m0 = mn0; m1 = mn1;
#pragma unroll
        for (int nv = 0; nv < 4; nv++) {
            o[nv][0] *= s0; o[nv][1] *= s0;
            o[nv][2] *= s1; o[nv][3] *= s1;
        }

        // ---- P = ex2(S-m) -> A-frags; O += P V (split, 3 passes) ----
#pragma unroll
        for (int kc = 0; kc < 4; kc++) {
            float p00 = ex2f(sc[2 * kc][0] - m0), p01 = ex2f(sc[2 * kc][1] - m0);
            float p02 = ex2f(sc[2 * kc][2] - m1), p03 = ex2f(sc[2 * kc][3] - m1);
            float p10 = ex2f(sc[2 * kc + 1][0] - m0), p11 = ex2f(sc[2 * kc + 1][1] - m0);
            float p12 = ex2f(sc[2 * kc + 1][2] - m1), p13 = ex2f(sc[2 * kc + 1][3] - m1);
            unsigned int a0 = pack2(p01, p00);
            unsigned int a1 = pack2(p03, p02);
            unsigned int a2 = pack2(p11, p10);
            unsigned int a3 = pack2(p13, p12);
            unsigned int a0l = pack2(p01 - unpk_hi(a0), p00 - unpk_lo(a0));
            unsigned int a1l = pack2(p03 - unpk_hi(a1), p02 - unpk_lo(a1));
            unsigned int a2l = pack2(p11 - unpk_hi(a2), p10 - unpk_lo(a2));
            unsigned int a3l = pack2(p13 - unpk_hi(a3), p12 - unpk_lo(a3));
#pragma unroll
            for (int nv = 0; nv < 4; nv++) {
                const char* vrow_h = Vhism + (nv * 8 + lq) * VST_;
                const char* vrow_l = Vlosm + (nv * 8 + lq) * VST_;
                int off = 32 * kc + lr * 4;
                unsigned int bh0 = *(const unsigned int*)(vrow_h + off);
                unsigned int bh1 = *(const unsigned int*)(vrow_h + off + 16);
                unsigned int bl0 = *(const unsigned int*)(vrow_l + off);
                unsigned int bl1 = *(const unsigned int*)(vrow_l + off + 16);
                mma16816(o[nv], a0, a1, a2, a3, bh0, bh1);
                mma16816(o[nv], a0l, a1l, a2l, a3l, bh0, bh1);
                mma16816(o[nv], a0, a1, a2, a3, bl0, bl1);
            }
        }
    }

    // ---- epilogue: cosine(o_row, mhat_row); softmax 1/l cancels in cosine ----
    int trow0 = qbase + wid * 16 + lq;
    int trow1 = trow0 + 8;
    float n20 = 0.f, dt0 = 0.f, n21 = 0.f, dt1 = 0.f;
    const float* mh0 = g_mhat + ((size_t)b * T_ + trow0) * M_;
    const float* mh1 = g_mhat + ((size_t)b * T_ + trow1) * M_;
#pragma unroll
    for (int nv = 0; nv < 4; nv++) {
        int col = nv * 8 + lr * 2;
        float2 w0 = *(const float2*)(mh0 + col);
        float2 w1 = *(const float2*)(mh1 + col);
        n20 += o[nv][0] * o[nv][0] + o[nv][1] * o[nv][1];
        dt0 += o[nv][0] * w0.x + o[nv][1] * w0.y;
        n21 += o[nv][2] * o[nv][2] + o[nv][3] * o[nv][3];
        dt1 += o[nv][2] * w1.x + o[nv][3] * w1.y;
    }
    n20 += __shfl_xor_sync(0xffffffffu, n20, 1);
    dt0 += __shfl_xor_sync(0xffffffffu, dt0, 1);
    n21 += __shfl_xor_sync(0xffffffffu, n21, 1);
    dt1 += __shfl_xor_sync(0xffffffffu, dt1, 1);
    n20 += __shfl_xor_sync(0xffffffffu, n20, 2);
    dt0 += __shfl_xor_sync(0xffffffffu, dt0, 2);
    n21 += __shfl_xor_sync(0xffffffffu, n21, 2);
    dt1 += __shfl_xor_sync(0xffffffffu, dt1, 2);
    if (lr == 0) {
        out[((size_t)b * T_ + trow0) * E_ + e] = dt0 / fmaxf(sqrtf(n20), EPS_);
        out[((size_t)b * T_ + trow1) * E_ + e] = dt1 / fmaxf(sqrtf(n21), EPS_);
    }
}

// ---------------- launch ----------------
extern "C" void kernel_launch(void* const* d_in, const int* in_sizes, int n_in,
                              void* d_out, int out_size) {
    const float* x      = (const float*)d_in[0];
    const float* hidden = (const float*)d_in[1];
    const float* memory = (const float*)d_in[2];
    const float* Wq     = (const float*)d_in[3];
    const float* Wk     = (const float*)d_in[4];
    const float* Wv     = (const float*)d_in[5];
    const float* iq     = (const float*)d_in[6];
    float* out = (float*)d_out;

    mem_kernel<<<(B_ * T_) / 256, 256>>>(x, memory, iq);
    qkv_kernel<<<dim3(T_ / 128, B_, E_), 128>>>(hidden, Wq, Wk, Wv);
    attn_kernel<<<dim3(T_ / TQ_, B_, E_), 256>>>(out);
}

// round 9
// speedup vs baseline: 3.9170x; 1.1442x over previous
#include <cuda_runtime.h>
#include <cuda_bf16.h>
#include <cstdint>

#define B_ 8
#define T_ 2048
#define H_ 64
#define M_ 32
#define S_ 20
#define E_ 3
#define IN_ 32
#define EPS_ 1e-8f
#define LOG2E_ 1.4426950408889634f

#define TQ_ 64           // q rows per CTA
#define TK_ 64           // keys per smem tile
#define NKT_ (T_ / TK_)  // 32

// ---------------- scratch (no cudaMalloc allowed) ----------------
__device__ __align__(16) float g_mhat[B_ * T_ * M_];
// Q,K rows: [hi 32 bf16 | lo 32 bf16] = 32 uints = 128B per row
__device__ __align__(16) unsigned int g_Qs[E_ * B_ * T_ * 32];
__device__ __align__(16) unsigned int g_Ks[E_ * B_ * T_ * 32];
// V transposed planes: [e][b][m][t/2] bf16 pairs
__device__ __align__(16) unsigned int g_Vthi[E_ * B_ * 32 * (T_ / 2)];
__device__ __align__(16) unsigned int g_Vtlo[E_ * B_ * 32 * (T_ / 2)];

// ---------------- helpers ----------------
static __device__ __forceinline__ float ex2f(float x) {
    float r; asm("ex2.approx.ftz.f32 %0, %1;" : "=f"(r) : "f"(x)); return r;
}
static __device__ __forceinline__ unsigned short f2bf(float f) {
    __nv_bfloat16 h = __float2bfloat16(f);
    return *reinterpret_cast<unsigned short*>(&h);
}
static __device__ __forceinline__ float bf2f(unsigned short u) {
    __nv_bfloat16 h; *reinterpret_cast<unsigned short*>(&h) = u;
    return __bfloat162float(h);
}
static __device__ __forceinline__ unsigned int pack2(float hi, float lo) {
    unsigned int d;
    asm("cvt.rn.bf16x2.f32 %0, %1, %2;" : "=r"(d) : "f"(hi), "f"(lo));
    return d;
}
static __device__ __forceinline__ float unpk_lo(unsigned int v) { return __uint_as_float(v << 16); }
static __device__ __forceinline__ float unpk_hi(unsigned int v) { return __uint_as_float(v & 0xffff0000u); }

static __device__ __forceinline__ unsigned long long pk2(float a, float b) {
    unsigned long long r;
    asm("mov.b64 %0, {%1, %2};" : "=l"(r) : "r"(__float_as_uint(a)), "r"(__float_as_uint(b)));
    return r;
}
static __device__ __forceinline__ void upk2(unsigned long long v, float& a, float& b) {
    unsigned lo, hi;
    asm("mov.b64 {%0, %1}, %2;" : "=r"(lo), "=r"(hi) : "l"(v));
    a = __uint_as_float(lo); b = __uint_as_float(hi);
}
static __device__ __forceinline__ unsigned long long ffma2(
        unsigned long long a, unsigned long long b, unsigned long long c) {
    unsigned long long d;
    asm("fma.rn.f32x2 %0, %1, %2, %3;" : "=l"(d) : "l"(a), "l"(b), "l"(c));
    return d;
}

static __device__ __forceinline__ void mma16816(
        float* c, unsigned int a0, unsigned int a1, unsigned int a2, unsigned int a3,
        unsigned int b0, unsigned int b1) {
    asm volatile(
        "mma.sync.aligned.m16n8k16.row.col.f32.bf16.bf16.f32 "
        "{%0,%1,%2,%3}, {%4,%5,%6,%7}, {%8,%9}, {%0,%1,%2,%3};"
        : "+f"(c[0]), "+f"(c[1]), "+f"(c[2]), "+f"(c[3])
        : "r"(a0), "r"(a1), "r"(a2), "r"(a3), "r"(b0), "r"(b1));
}

static __device__ __forceinline__ uint32_t smem_u32(const void* p) {
    uint32_t a;
    asm("{ .reg .u64 t; cvta.to.shared.u64 t, %1; cvt.u32.u64 %0, t; }" : "=r"(a) : "l"(p));
    return a;
}
static __device__ __forceinline__ void cpa16(uint32_t s, const void* g) {
    asm volatile("cp.async.cg.shared.global [%0], [%1], 16;" :: "r"(s), "l"(g));
}
#define CPA_COMMIT() asm volatile("cp.async.commit_group;" ::: "memory")
#define CPA_WAIT0()  asm volatile("cp.async.wait_group 0;" ::: "memory")

static __device__ __forceinline__ float wsum(float v) {
    v += __shfl_xor_sync(0xffffffffu, v, 16);
    v += __shfl_xor_sync(0xffffffffu, v, 8);
    v += __shfl_xor_sync(0xffffffffu, v, 4);
    v += __shfl_xor_sync(0xffffffffu, v, 2);
    v += __shfl_xor_sync(0xffffffffu, v, 1);
    return v;
}

// ---------------- kernel A: memories -> g_mhat (warp per row) ----------------
__global__ __launch_bounds__(256) void mem_kernel(
        const float* __restrict__ x,
        const float* __restrict__ memory,
        const float* __restrict__ iq) {
    __shared__ float iqs[IN_ * M_];   // iq[i][m], row-major as given
    __shared__ float sm[S_ * M_];
    int tid = threadIdx.x;
    for (int n = tid; n < IN_ * M_; n += 256) iqs[n] = iq[n];
    for (int n = tid; n < S_ * M_; n += 256) sm[n] = memory[n];
    __syncthreads();

    int wid = tid >> 5, lane = tid & 31;
    int bt = blockIdx.x * 8 + wid;                 // one warp per (b,t) row
    float xv = x[(size_t)bt * IN_ + lane];
    float qv = 0.f;
#pragma unroll
    for (int i = 0; i < IN_; i++)
        qv = fmaf(__shfl_sync(0xffffffffu, xv, i), iqs[i * M_ + lane], qv);

    float s[S_];
    float mx = -3e38f;
#pragma unroll
    for (int j = 0; j < S_; j++) {
        float p = wsum(qv * sm[j * M_ + lane]);
        s[j] = p;
        mx = fmaxf(mx, p);
    }
    float L = 0.f;
#pragma unroll
    for (int j = 0; j < S_; j++) {
        s[j] = ex2f((s[j] - mx) * LOG2E_);
        L += s[j];
    }
    float macc = 0.f;
#pragma unroll
    for (int j = 0; j < S_; j++) macc = fmaf(s[j], sm[j * M_ + lane], macc);
    macc *= (1.0f / L);
    float ss = wsum(macc * macc);
    float rinv = 1.0f / fmaxf(sqrtf(ss), EPS_);
    g_mhat[(size_t)bt * M_ + lane] = macc * rinv;
}

// ---------------- kernel B: QKV projection + split/pack/transpose ----------------
static __device__ __forceinline__ void split_pack_row(const float* a, unsigned int* dst) {
#pragma unroll
    for (int i = 0; i < 16; i++) {
        unsigned short h0 = f2bf(a[2 * i]), h1 = f2bf(a[2 * i + 1]);
        dst[i] = (unsigned)h0 | ((unsigned)h1 << 16);
        float l0 = a[2 * i] - bf2f(h0), l1 = a[2 * i + 1] - bf2f(h1);
        dst[16 + i] = (unsigned)f2bf(l0) | ((unsigned)f2bf(l1) << 16);
    }
}

__global__ __launch_bounds__(128) void qkv_kernel(
        const float* __restrict__ hidden,
        const float* __restrict__ Wq,
        const float* __restrict__ Wk,
        const float* __restrict__ Wv) {
    __shared__ unsigned long long w2[3][H_ * 16];   // packed float pairs, 24KB
    __shared__ float sv[128 * 32];                  // V rows for transpose
    int e = blockIdx.z, b = blockIdx.y;
    int tid = threadIdx.x;
    const float* Ws[3] = {Wq, Wk, Wv};
    for (int p = 0; p < 3; p++) {
        const unsigned long long* src = (const unsigned long long*)(Ws[p] + e * H_ * M_);
        for (int n = tid; n < H_ * 16; n += 128) w2[p][n] = src[n];
    }
    __syncthreads();

    int t0 = blockIdx.x * 128;
    int t = t0 + tid;
    size_t row = (size_t)(e * B_ + b) * T_ + t;
    float h[H_];
    const float4* h4 = (const float4*)(hidden + row * H_);
#pragma unroll
    for (int i = 0; i < H_ / 4; i++) {
        float4 v = h4[i];
        h[4 * i] = v.x; h[4 * i + 1] = v.y; h[4 * i + 2] = v.z; h[4 * i + 3] = v.w;
    }
    for (int p = 0; p < 3; p++) {
        unsigned long long acc2[16];
#pragma unroll
        for (int m = 0; m < 16; m++) acc2[m] = 0ull;
#pragma unroll
        for (int i = 0; i < H_; i++) {
            unsigned long long h2 = pk2(h[i], h[i]);
#pragma unroll
            for (int m = 0; m < 16; m++)
                acc2[m] = ffma2(h2, w2[p][i * 16 + m], acc2[m]);
        }
        float acc[M_];
#pragma unroll
        for (int m = 0; m < 16; m++) upk2(acc2[m], acc[2 * m], acc[2 * m + 1]);

        if (p == 0) {
#pragma unroll
            for (int m = 0; m < M_; m++) acc[m] *= LOG2E_;   // log2-domain scores
            unsigned int pk[32];
            split_pack_row(acc, pk);
            uint4* o = (uint4*)(g_Qs + row * 32);
#pragma unroll
            for (int i = 0; i < 8; i++) o[i] = ((uint4*)pk)[i];
        } else if (p == 1) {
            unsigned int pk[32];
            split_pack_row(acc, pk);
            uint4* o = (uint4*)(g_Ks + row * 32);
#pragma unroll
            for (int i = 0; i < 8; i++) o[i] = ((uint4*)pk)[i];
        } else {
#pragma unroll
            for (int m = 0; m < M_; m++) sv[tid * 32 + m] = acc[m];
        }
    }
    __syncthreads();
    // transpose V: thread owns (m, t-chunk of 32)
    int m = tid & 31, tc = tid >> 5;
    size_t vbase = ((size_t)(e * B_ + b) * 32 + m) * (T_ / 2) + (size_t)(t0 + tc * 32) / 2;
#pragma unroll
    for (int j = 0; j < 16; j++) {
        float f0 = sv[(tc * 32 + 2 * j) * 32 + m];
        float f1 = sv[(tc * 32 + 2 * j + 1) * 32 + m];
        unsigned short h0 = f2bf(f0), h1 = f2bf(f1);
        g_Vthi[vbase + j] = (unsigned)h0 | ((unsigned)h1 << 16);
        float l0 = f0 - bf2f(h0), l1 = f1 - bf2f(h1);
        g_Vtlo[vbase + j] = (unsigned)f2bf(l0) | ((unsigned)f2bf(l1) << 16);
    }
}

// ---------------- kernel C: HMMA flash attention + fused cosine ----------------
#define KST_ 144
#define VST_ 144

__global__ __launch_bounds__(128, 4) void attn_kernel(float* __restrict__ out) {
    __shared__ __align__(16) char Qsm[TQ_ * 128];          // 8KB
    __shared__ __align__(16) char Ksm[2][TK_ * KST_];      // 18KB
    __shared__ __align__(16) char Vhism[2][32 * VST_];     // 9KB
    __shared__ __align__(16) char Vlosm[2][32 * VST_];     // 9KB

    int tid = threadIdx.x, wid = tid >> 5, lane = tid & 31;
    int e = blockIdx.z, b = blockIdx.y;
    int qbase = blockIdx.x * TQ_;
    size_t eb = (size_t)(e * B_ + b);
    int lq = lane >> 2;      // 0..7
    int lr = lane & 3;       // 0..3

    const uint4* kg = (const uint4*)g_Ks + eb * T_ * 8;
    const uint4* vhg = (const uint4*)g_Vthi + eb * 32 * 256;
    const uint4* vlg = (const uint4*)g_Vtlo + eb * 32 * 256;

    uint32_t ksb[2] = {smem_u32(Ksm[0]), smem_u32(Ksm[1])};
    uint32_t vhb[2] = {smem_u32(Vhism[0]), smem_u32(Vhism[1])};
    uint32_t vlb[2] = {smem_u32(Vlosm[0]), smem_u32(Vlosm[1])};

    // ---- prefetch tile 0 via cp.async ----
    {
#pragma unroll
        for (int j = 0; j < 4; j++) {
            int i = tid + j * 128;
            int r = i >> 3, ch = i & 7;
            cpa16(ksb[0] + r * KST_ + ch * 16, kg + (size_t)r * 8 + ch);
        }
#pragma unroll
        for (int j = 0; j < 2; j++) {
            int i = tid + j * 128;
            int m = i >> 3, ch = i & 7;
            cpa16(vhb[0] + m * VST_ + ch * 16, vhg + (size_t)m * 256 + ch);
            cpa16(vlb[0] + m * VST_ + ch * 16, vlg + (size_t)m * 256 + ch);
        }
        CPA_COMMIT();
    }

    // ---- load Q tile (plain) ----
    {
        const uint4* qg = (const uint4*)g_Qs + (eb * T_ + qbase) * 8;
#pragma unroll
        for (int j = 0; j < 4; j++) {
            int i = tid + j * 128;
            int r = i >> 3, ch = i & 7;
            *(uint4*)(Qsm + r * 128 + ch * 16) = qg[(size_t)r * 8 + ch];
        }
    }
    __syncthreads();

    // ---- persistent Q A-fragments ----
    unsigned int qhi[2][4], qlo[2][4];
    {
        int r0 = wid * 16 + lq;
#pragma unroll
        for (int kc = 0; kc < 2; kc++) {
            int off = (8 * kc + lr) * 4;
            qhi[kc][0] = *(const unsigned int*)(Qsm + r0 * 128 + off);
            qhi[kc][1] = *(const unsigned int*)(Qsm + (r0 + 8) * 128 + off);
            qhi[kc][2] = *(const unsigned int*)(Qsm + r0 * 128 + off + 16);
            qhi[kc][3] = *(const unsigned int*)(Qsm + (r0 + 8) * 128 + off + 16);
            qlo[kc][0] = *(const unsigned int*)(Qsm + r0 * 128 + 64 + off);
            qlo[kc][1] = *(const unsigned int*)(Qsm + (r0 + 8) * 128 + 64 + off);
            qlo[kc][2] = *(const unsigned int*)(Qsm + r0 * 128 + 64 + off + 16);
            qlo[kc][3] = *(const unsigned int*)(Qsm + (r0 + 8) * 128 + 64 + off + 16);
        }
    }

    float o[4][4];
#pragma unroll
    for (int i = 0; i < 4; i++)
#pragma unroll
        for (int j = 0; j < 4; j++) o[i][j] = 0.f;
    float m0 = -1e30f, m1 = -1e30f;

    for (int kt = 0; kt < NKT_; kt++) {
        int st = kt & 1;
        CPA_WAIT0();
        __syncthreads();
        // ---- prefetch next tile into other buffer ----
        if (kt + 1 < NKT_) {
            int ns = st ^ 1;
            int nk = kt + 1;
#pragma unroll
            for (int j = 0; j < 4; j++) {
                int i = tid + j * 128;
                int r = i >> 3, ch = i & 7;
                cpa16(ksb[ns] + r * KST_ + ch * 16, kg + (size_t)(nk * TK_ + r) * 8 + ch);
            }
#pragma unroll
            for (int j = 0; j < 2; j++) {
                int i = tid + j * 128;
                int m = i >> 3, ch = i & 7;
                cpa16(vhb[ns] + m * VST_ + ch * 16, vhg + (size_t)m * 256 + nk * 8 + ch);
                cpa16(vlb[ns] + m * VST_ + ch * 16, vlg + (size_t)m * 256 + nk * 8 + ch);
            }
            CPA_COMMIT();
        }

        // ---- S = Q K^T (split bf16, 3 passes) ----
        float sc[8][4];
#pragma unroll
        for (int n = 0; n < 8; n++) {
            sc[n][0] = sc[n][1] = sc[n][2] = sc[n][3] = 0.f;
            const char* rowp = Ksm[st] + (n * 8 + lq) * KST_;
#pragma unroll
            for (int kc = 0; kc < 2; kc++) {
                int off = 32 * kc + lr * 4;
                unsigned int bh0 = *(const unsigned int*)(rowp + off);
                unsigned int bh1 = *(const unsigned int*)(rowp + off + 16);
                unsigned int bl0 = *(const unsigned int*)(rowp + 64 + off);
                unsigned int bl1 = *(const unsigned int*)(rowp + 64 + off + 16);
                mma16816(sc[n], qhi[kc][0], qhi[kc][1], qhi[kc][2], qhi[kc][3], bh0, bh1);
                mma16816(sc[n], qlo[kc][0], qlo[kc][1], qlo[kc][2], qlo[kc][3], bh0, bh1);
                mma16816(sc[n], qhi[kc][0], qhi[kc][1], qhi[kc][2], qhi[kc][3], bl0, bl1);
            }
        }

        // ---- online max (log2 domain), rescale O ----
        float mt0 = -1e30f, mt1 = -1e30f;
#pragma unroll
        for (int n = 0; n < 8; n++) {
            mt0 = fmaxf(mt0, fmaxf(sc[n][0], sc[n][1]));
            mt1 = fmaxf(mt1, fmaxf(sc[n][2], sc[n][3]));
        }
        mt0 = fmaxf(mt0, __shfl_xor_sync(0xffffffffu, mt0, 1));
        mt0 = fmaxf(mt0, __shfl_xor_sync(0xffffffffu, mt0, 2));
        mt1 = fmaxf(mt1, __shfl_xor_sync(0xffffffffu, mt1, 1));
        mt1 = fmaxf(mt1, __shfl_xor_sync(0xffffffffu, mt1, 2));
        float mn0 = fmaxf(m0, mt0), mn1 = fmaxf(m1, mt1);
        float s0 = ex2f(m0 - mn0), s1 = ex2f(m1 - mn1);
        m0 = mn0; m1 = mn1;
#pragma unroll
        for (int nv = 0; nv < 4; nv++) {
            o[nv][0] *= s0; o[nv][1] *= s0;
            o[nv][2] *= s1; o[nv][3] *= s1;
        }

        // ---- P = ex2(S-m) -> A-frags; O += P V (split, 3 passes) ----
#pragma unroll
        for (int kc = 0; kc < 4; kc++) {
            float p00 = ex2f(sc[2 * kc][0] - m0), p01 = ex2f(sc[2 * kc][1] - m0);
            float p02 = ex2f(sc[2 * kc][2] - m1), p03 = ex2f(sc[2 * kc][3] - m1);
            float p10 = ex2f(sc[2 * kc + 1][0] - m0), p11 = ex2f(sc[2 * kc + 1][1] - m0);
            float p12 = ex2f(sc[2 * kc + 1][2] - m1), p13 = ex2f(sc[2 * kc + 1][3] - m1);
            unsigned int a0 = pack2(p01, p00);
            unsigned int a1 = pack2(p03, p02);
            unsigned int a2 = pack2(p11, p10);
            unsigned int a3 = pack2(p13, p12);
            unsigned int a0l = pack2(p01 - unpk_hi(a0), p00 - unpk_lo(a0));
            unsigned int a1l = pack2(p03 - unpk_hi(a1), p02 - unpk_lo(a1));
            unsigned int a2l = pack2(p11 - unpk_hi(a2), p10 - unpk_lo(a2));
            unsigned int a3l = pack2(p13 - unpk_hi(a3), p12 - unpk_lo(a3));
#pragma unroll
            for (int nv = 0; nv < 4; nv++) {
                const char* vrow_h = Vhism[st] + (nv * 8 + lq) * VST_;
                const char* vrow_l = Vlosm[st] + (nv * 8 + lq) * VST_;
                int off = 32 * kc + lr * 4;
                unsigned int bh0 = *(const unsigned int*)(vrow_h + off);
                unsigned int bh1 = *(const unsigned int*)(vrow_h + off + 16);
                unsigned int bl0 = *(const unsigned int*)(vrow_l + off);
                unsigned int bl1 = *(const unsigned int*)(vrow_l + off + 16);
                mma16816(o[nv], a0, a1, a2, a3, bh0, bh1);
                mma16816(o[nv], a0l, a1l, a2l, a3l, bh0, bh1);
                mma16816(o[nv], a0, a1, a2, a3, bl0, bl1);
            }
        }
    }

    // ---- epilogue: cosine(o_row, mhat_row); softmax 1/l cancels in cosine ----
    int trow0 = qbase + wid * 16 + lq;
    int trow1 = trow0 + 8;
    float n20 = 0.f, dt0 = 0.f, n21 = 0.f, dt1 = 0.f;
    const float* mh0 = g_mhat + ((size_t)b * T_ + trow0) * M_;
    const float* mh1 = g_mhat + ((size_t)b * T_ + trow1) * M_;
#pragma unroll
    for (int nv = 0; nv < 4; nv++) {
        int col = nv * 8 + lr * 2;
        float2 w0 = *(const float2*)(mh0 + col);
        float2 w1 = *(const float2*)(mh1 + col);
        n20 += o[nv][0] * o[nv][0] + o[nv][1] * o[nv][1];
        dt0 += o[nv][0] * w0.x + o[nv][1] * w0.y;
        n21 += o[nv][2] * o[nv][2] + o[nv][3] * o[nv][3];
        dt1 += o[nv][2] * w1.x + o[nv][3] * w1.y;
    }
    n20 += __shfl_xor_sync(0xffffffffu, n20, 1);
    dt0 += __shfl_xor_sync(0xffffffffu, dt0, 1);
    n21 += __shfl_xor_sync(0xffffffffu, n21, 1);
    dt1 += __shfl_xor_sync(0xffffffffu, dt1, 1);
    n20 += __shfl_xor_sync(0xffffffffu, n20, 2);
    dt0 += __shfl_xor_sync(0xffffffffu, dt0, 2);
    n21 += __shfl_xor_sync(0xffffffffu, n21, 2);
    dt1 += __shfl_xor_sync(0xffffffffu, dt1, 2);
    if (lr == 0) {
        out[((size_t)b * T_ + trow0) * E_ + e] = dt0 / fmaxf(sqrtf(n20), EPS_);
        out[((size_t)b * T_ + trow1) * E_ + e] = dt1 / fmaxf(sqrtf(n21), EPS_);
    }
}

// ---------------- launch ----------------
extern "C" void kernel_launch(void* const* d_in, const int* in_sizes, int n_in,
                              void* d_out, int out_size) {
    const float* x      = (const float*)d_in[0];
    const float* hidden = (const float*)d_in[1];
    const float* memory = (const float*)d_in[2];
    const float* Wq     = (const float*)d_in[3];
    const float* Wk     = (const float*)d_in[4];
    const float* Wv     = (const float*)d_in[5];
    const float* iq     = (const float*)d_in[6];
    float* out = (float*)d_out;

    mem_kernel<<<(B_ * T_) / 8, 256>>>(x, memory, iq);   // one warp per row: 2048 blocks
    qkv_kernel<<<dim3(T_ / 128, B_, E_), 128>>>(hidden, Wq, Wk, Wv);
    attn_kernel<<<dim3(T_ / TQ_, B_, E_), 128>>>(out);
}

// round 13
// speedup vs baseline: 4.3444x; 1.1091x over previous
#include <cuda_runtime.h>
#include <cuda_bf16.h>
#include <cstdint>

#define B_ 8
#define T_ 2048
#define H_ 64
#define M_ 32
#define S_ 20
#define E_ 3
#define IN_ 32
#define EPS_ 1e-8f
#define LOG2E_ 1.4426950408889634f

#define TQ_ 64           // q rows per CTA
#define TK_ 64           // keys per smem tile
#define NKT_ (T_ / TK_)  // 32

// ---------------- scratch (no cudaMalloc allowed) ----------------
__device__ __align__(16) float g_mhat[B_ * T_ * M_];
// Q,K rows: [hi 32 bf16 | lo 32 bf16] = 32 uints = 128B per row (group-permuted)
__device__ __align__(16) unsigned int g_Qs[E_ * B_ * T_ * 32];
__device__ __align__(16) unsigned int g_Ks[E_ * B_ * T_ * 32];
// V transposed planes: [e][b][m][t/2] bf16 pairs (group-permuted)
__device__ __align__(16) unsigned int g_Vthi[E_ * B_ * 32 * (T_ / 2)];
__device__ __align__(16) unsigned int g_Vtlo[E_ * B_ * 32 * (T_ / 2)];

// ---------------- helpers ----------------
static __device__ __forceinline__ float ex2f(float x) {
    float r; asm("ex2.approx.ftz.f32 %0, %1;" : "=f"(r) : "f"(x)); return r;
}
static __device__ __forceinline__ unsigned short f2bf(float f) {
    __nv_bfloat16 h = __float2bfloat16(f);
    return *reinterpret_cast<unsigned short*>(&h);
}
static __device__ __forceinline__ float bf2f(unsigned short u) {
    __nv_bfloat16 h; *reinterpret_cast<unsigned short*>(&h) = u;
    return __bfloat162float(h);
}
static __device__ __forceinline__ unsigned int pack2(float hi, float lo) {
    unsigned int d;
    asm("cvt.rn.bf16x2.f32 %0, %1, %2;" : "=r"(d) : "f"(hi), "f"(lo));
    return d;
}
static __device__ __forceinline__ float unpk_lo(unsigned int v) { return __uint_as_float(v << 16); }
static __device__ __forceinline__ float unpk_hi(unsigned int v) { return __uint_as_float(v & 0xffff0000u); }

static __device__ __forceinline__ unsigned long long pk2(float a, float b) {
    unsigned long long r;
    asm("mov.b64 %0, {%1, %2};" : "=l"(r) : "r"(__float_as_uint(a)), "r"(__float_as_uint(b)));
    return r;
}
static __device__ __forceinline__ void upk2(unsigned long long v, float& a, float& b) {
    unsigned lo, hi;
    asm("mov.b64 {%0, %1}, %2;" : "=r"(lo), "=r"(hi) : "l"(v));
    a = __uint_as_float(lo); b = __uint_as_float(hi);
}
static __device__ __forceinline__ unsigned long long ffma2(
        unsigned long long a, unsigned long long b, unsigned long long c) {
    unsigned long long d;
    asm("fma.rn.f32x2 %0, %1, %2, %3;" : "=l"(d) : "l"(a), "l"(b), "l"(c));
    return d;
}

static __device__ __forceinline__ void mma16816(
        float* c, unsigned int a0, unsigned int a1, unsigned int a2, unsigned int a3,
        unsigned int b0, unsigned int b1) {
    asm volatile(
        "mma.sync.aligned.m16n8k16.row.col.f32.bf16.bf16.f32 "
        "{%0,%1,%2,%3}, {%4,%5,%6,%7}, {%8,%9}, {%0,%1,%2,%3};"
        : "+f"(c[0]), "+f"(c[1]), "+f"(c[2]), "+f"(c[3])
        : "r"(a0), "r"(a1), "r"(a2), "r"(a3), "r"(b0), "r"(b1));
}

static __device__ __forceinline__ uint32_t smem_u32(const void* p) {
    uint32_t a;
    asm("{ .reg .u64 t; cvta.to.shared.u64 t, %1; cvt.u32.u64 %0, t; }" : "=r"(a) : "l"(p));
    return a;
}
static __device__ __forceinline__ void cpa16(uint32_t s, const void* g) {
    asm volatile("cp.async.cg.shared.global [%0], [%1], 16;" :: "r"(s), "l"(g));
}
#define CPA_COMMIT() asm volatile("cp.async.commit_group;" ::: "memory")
#define CPA_WAIT0()  asm volatile("cp.async.wait_group 0;" ::: "memory")

// group-of-8 word permutation: input word i -> position 2*(i&3) + (i>>2).
// Makes fragment word pairs (i, i+4) adjacent -> LDS.64 in attn.
static __device__ __forceinline__ int perm8(int i) { return ((i & 3) << 1) | (i >> 2); }

// ---------------- prep kernel: qkv (z=0..2) + mem (z=3) ----------------
static __device__ __forceinline__ void split_pack_row(const float* a, unsigned int* dst) {
#pragma unroll
    for (int i = 0; i < 16; i++) {
        int pos = (i & 8) + perm8(i & 7);
        unsigned short h0 = f2bf(a[2 * i]), h1 = f2bf(a[2 * i + 1]);
        dst[pos] = (unsigned)h0 | ((unsigned)h1 << 16);
        float l0 = a[2 * i] - bf2f(h0), l1 = a[2 * i + 1] - bf2f(h1);
        dst[16 + pos] = (unsigned)f2bf(l0) | ((unsigned)f2bf(l1) << 16);
    }
}

__global__ __launch_bounds__(128) void prep_kernel(
        const float* __restrict__ x,
        const float* __restrict__ memory,
        const float* __restrict__ iq,
        const float* __restrict__ hidden,
        const float* __restrict__ Wq,
        const float* __restrict__ Wk,
        const float* __restrict__ Wv) {
    __shared__ unsigned long long w2[3][H_ * 16];   // qkv: packed weight pairs (24KB)
    __shared__ float sv[128 * 32];                  // qkv: V rows for transpose (16KB)
    int tid = threadIdx.x;

    if (blockIdx.z == 3) {
        // ================= mem path: thread per (b,t) row =================
        float* iqs = (float*)w2[0];            // IN*M floats
        float* smem_m = (float*)w2[0] + IN_ * M_;  // S*M floats
        for (int n = tid; n < IN_ * M_; n += 128) iqs[n] = iq[n];
        for (int n = tid; n < S_ * M_; n += 128) smem_m[n] = memory[n];
        __syncthreads();

        int bt = (blockIdx.y * 16 + blockIdx.x) * 128 + tid;   // 0..16383
        float xr[IN_];
        const float4* x4 = (const float4*)(x + (size_t)bt * IN_);
#pragma unroll
        for (int i = 0; i < IN_ / 4; i++) {
            float4 v = x4[i];
            xr[4 * i] = v.x; xr[4 * i + 1] = v.y; xr[4 * i + 2] = v.z; xr[4 * i + 3] = v.w;
        }
        float qv[M_];
#pragma unroll
        for (int m = 0; m < M_; m++) qv[m] = 0.f;
#pragma unroll
        for (int i = 0; i < IN_; i++) {
            float xv = xr[i];
#pragma unroll
            for (int m = 0; m < M_; m++) qv[m] = fmaf(xv, iqs[i * M_ + m], qv[m]);
        }
        // slot dots once, 4-way split accumulators
        float s[S_];
        float mx = -3e38f;
#pragma unroll
        for (int j = 0; j < S_; j++) {
            float d0 = 0.f, d1 = 0.f, d2 = 0.f, d3 = 0.f;
            const float* r = smem_m + j * M_;
#pragma unroll
            for (int m = 0; m < M_; m += 4) {
                d0 = fmaf(qv[m], r[m], d0);
                d1 = fmaf(qv[m + 1], r[m + 1], d1);
                d2 = fmaf(qv[m + 2], r[m + 2], d2);
                d3 = fmaf(qv[m + 3], r[m + 3], d3);
            }
            s[j] = (d0 + d1) + (d2 + d3);
            mx = fmaxf(mx, s[j]);
        }
        float L = 0.f;
#pragma unroll
        for (int j = 0; j < S_; j++) {
            s[j] = ex2f((s[j] - mx) * LOG2E_);
            L += s[j];
        }
        float macc[M_];
#pragma unroll
        for (int m = 0; m < M_; m++) macc[m] = 0.f;
#pragma unroll
        for (int j = 0; j < S_; j++) {
            float p = s[j];
            const float* r = smem_m + j * M_;
#pragma unroll
            for (int m = 0; m < M_; m++) macc[m] = fmaf(p, r[m], macc[m]);
        }
        float invL = 1.0f / L;
        float ss = 0.f;
#pragma unroll
        for (int m = 0; m < M_; m++) {
            macc[m] *= invL;
            ss += macc[m] * macc[m];
        }
        float rinv = 1.0f / fmaxf(sqrtf(ss), EPS_);
        float4* o4 = (float4*)(g_mhat + (size_t)bt * M_);
#pragma unroll
        for (int i = 0; i < M_ / 4; i++) {
            float4 v;
            v.x = macc[4 * i] * rinv; v.y = macc[4 * i + 1] * rinv;
            v.z = macc[4 * i + 2] * rinv; v.w = macc[4 * i + 3] * rinv;
            o4[i] = v;
        }
        return;
    }

    // ================= qkv path =================
    int e = blockIdx.z, b = blockIdx.y;
    const float* Ws[3] = {Wq, Wk, Wv};
    for (int p = 0; p < 3; p++) {
        const unsigned long long* src = (const unsigned long long*)(Ws[p] + e * H_ * M_);
        for (int n = tid; n < H_ * 16; n += 128) w2[p][n] = src[n];
    }
    __syncthreads();

    int t0 = blockIdx.x * 128;
    int t = t0 + tid;
    size_t row = (size_t)(e * B_ + b) * T_ + t;
    float h[H_];
    const float4* h4 = (const float4*)(hidden + row * H_);
#pragma unroll
    for (int i = 0; i < H_ / 4; i++) {
        float4 v = h4[i];
        h[4 * i] = v.x; h[4 * i + 1] = v.y; h[4 * i + 2] = v.z; h[4 * i + 3] = v.w;
    }
    for (int p = 0; p < 3; p++) {
        unsigned long long acc2[16];
#pragma unroll
        for (int m = 0; m < 16; m++) acc2[m] = 0ull;
#pragma unroll
        for (int i = 0; i < H_; i++) {
            unsigned long long h2 = pk2(h[i], h[i]);
#pragma unroll
            for (int m = 0; m < 16; m++)
                acc2[m] = ffma2(h2, w2[p][i * 16 + m], acc2[m]);
        }
        float acc[M_];
#pragma unroll
        for (int m = 0; m < 16; m++) upk2(acc2[m], acc[2 * m], acc[2 * m + 1]);

        if (p == 0) {
#pragma unroll
            for (int m = 0; m < M_; m++) acc[m] *= LOG2E_;   // log2-domain scores
            unsigned int pk[32];
            split_pack_row(acc, pk);
            uint4* o = (uint4*)(g_Qs + row * 32);
#pragma unroll
            for (int i = 0; i < 8; i++) o[i] = ((uint4*)pk)[i];
        } else if (p == 1) {
            unsigned int pk[32];
            split_pack_row(acc, pk);
            uint4* o = (uint4*)(g_Ks + row * 32);
#pragma unroll
            for (int i = 0; i < 8; i++) o[i] = ((uint4*)pk)[i];
        } else {
#pragma unroll
            for (int m = 0; m < M_; m++) sv[tid * 32 + m] = acc[m];
        }
    }
    __syncthreads();
    // transpose V: thread owns (m, t-chunk of 32); write group-permuted words
    int m = tid & 31, tc = tid >> 5;
    size_t vbase = ((size_t)(e * B_ + b) * 32 + m) * (T_ / 2) + (size_t)(t0 + tc * 32) / 2;
#pragma unroll
    for (int j = 0; j < 16; j++) {
        int pos = (j & 8) + perm8(j & 7);
        float f0 = sv[(tc * 32 + 2 * j) * 32 + m];
        float f1 = sv[(tc * 32 + 2 * j + 1) * 32 + m];
        unsigned short h0 = f2bf(f0), h1 = f2bf(f1);
        g_Vthi[vbase + pos] = (unsigned)h0 | ((unsigned)h1 << 16);
        float l0 = f0 - bf2f(h0), l1 = f1 - bf2f(h1);
        g_Vtlo[vbase + pos] = (unsigned)f2bf(l0) | ((unsigned)f2bf(l1) << 16);
    }
}

// ---------------- kernel C: HMMA flash attention + fused cosine ----------------
#define KST_ 160
#define VST_ 160

__global__ __launch_bounds__(128, 4) void attn_kernel(float* __restrict__ out) {
    __shared__ __align__(16) char Qsm[TQ_ * 128];          // 8KB
    __shared__ __align__(16) char Ksm[2][TK_ * KST_];      // 20KB
    __shared__ __align__(16) char Vhism[2][32 * VST_];     // 10KB
    __shared__ __align__(16) char Vlosm[2][32 * VST_];     // 10KB

    int tid = threadIdx.x, wid = tid >> 5, lane = tid & 31;
    int e = blockIdx.z, b = blockIdx.y;
    int qbase = blockIdx.x * TQ_;
    size_t eb = (size_t)(e * B_ + b);
    int lq = lane >> 2;      // 0..7
    int lr = lane & 3;       // 0..3

    const uint4* kg = (const uint4*)g_Ks + eb * T_ * 8;
    const uint4* vhg = (const uint4*)g_Vthi + eb * 32 * 256;
    const uint4* vlg = (const uint4*)g_Vtlo + eb * 32 * 256;

    uint32_t ksb[2] = {smem_u32(Ksm[0]), smem_u32(Ksm[1])};
    uint32_t vhb[2] = {smem_u32(Vhism[0]), smem_u32(Vhism[1])};
    uint32_t vlb[2] = {smem_u32(Vlosm[0]), smem_u32(Vlosm[1])};

    // ---- prefetch tile 0 via cp.async ----
    {
#pragma unroll
        for (int j = 0; j < 4; j++) {
            int i = tid + j * 128;
            int r = i >> 3, ch = i & 7;
            cpa16(ksb[0] + r * KST_ + ch * 16, kg + (size_t)r * 8 + ch);
        }
#pragma unroll
        for (int j = 0; j < 2; j++) {
            int i = tid + j * 128;
            int m = i >> 3, ch = i & 7;
            cpa16(vhb[0] + m * VST_ + ch * 16, vhg + (size_t)m * 256 + ch);
            cpa16(vlb[0] + m * VST_ + ch * 16, vlg + (size_t)m * 256 + ch);
        }
        CPA_COMMIT();
    }

    // ---- load Q tile (plain) ----
    {
        const uint4* qg = (const uint4*)g_Qs + (eb * T_ + qbase) * 8;
#pragma unroll
        for (int j = 0; j < 4; j++) {
            int i = tid + j * 128;
            int r = i >> 3, ch = i & 7;
            *(uint4*)(Qsm + r * 128 + ch * 16) = qg[(size_t)r * 8 + ch];
        }
    }
    __syncthreads();

    // ---- persistent Q A-fragments (pairs adjacent after perm) ----
    unsigned int qhi[2][4], qlo[2][4];
    {
        int r0 = wid * 16 + lq;
#pragma unroll
        for (int kc = 0; kc < 2; kc++) {
            int off = kc * 32 + lr * 8;
            uint2 v0 = *(const uint2*)(Qsm + r0 * 128 + off);
            uint2 v1 = *(const uint2*)(Qsm + (r0 + 8) * 128 + off);
            qhi[kc][0] = v0.x; qhi[kc][1] = v1.x; qhi[kc][2] = v0.y; qhi[kc][3] = v1.y;
            uint2 w0 = *(const uint2*)(Qsm + r0 * 128 + 64 + off);
            uint2 w1 = *(const uint2*)(Qsm + (r0 + 8) * 128 + 64 + off);
            qlo[kc][0] = w0.x; qlo[kc][1] = w1.x; qlo[kc][2] = w0.y; qlo[kc][3] = w1.y;
        }
    }

    float o[4][4];
#pragma unroll
    for (int i = 0; i < 4; i++)
#pragma unroll
        for (int j = 0; j < 4; j++) o[i][j] = 0.f;
    float m0 = -1e30f, m1 = -1e30f;

    for (int kt = 0; kt < NKT_; kt++) {
        int st = kt & 1;
        CPA_WAIT0();
        __syncthreads();
        // ---- prefetch next tile into other buffer ----
        if (kt + 1 < NKT_) {
            int ns = st ^ 1;
            int nk = kt + 1;
#pragma unroll
            for (int j = 0; j < 4; j++) {
                int i = tid + j * 128;
                int r = i >> 3, ch = i & 7;
                cpa16(ksb[ns] + r * KST_ + ch * 16, kg + (size_t)(nk * TK_ + r) * 8 + ch);
            }
#pragma unroll
            for (int j = 0; j < 2; j++) {
                int i = tid + j * 128;
                int m = i >> 3, ch = i & 7;
                cpa16(vhb[ns] + m * VST_ + ch * 16, vhg + (size_t)m * 256 + nk * 8 + ch);
                cpa16(vlb[ns] + m * VST_ + ch * 16, vlg + (size_t)m * 256 + nk * 8 + ch);
            }
            CPA_COMMIT();
        }

        // ---- S = Q K^T (split bf16, 3 passes) ----
        float sc[8][4];
#pragma unroll
        for (int n = 0; n < 8; n++) {
            sc[n][0] = sc[n][1] = sc[n][2] = sc[n][3] = 0.f;
            const char* rowp = Ksm[st] + (n * 8 + lq) * KST_;
#pragma unroll
            for (int kc = 0; kc < 2; kc++) {
                int off = kc * 32 + lr * 8;
                uint2 bh = *(const uint2*)(rowp + off);
                uint2 bl = *(const uint2*)(rowp + 64 + off);
                mma16816(sc[n], qhi[kc][0], qhi[kc][1], qhi[kc][2], qhi[kc][3], bh.x, bh.y);
                mma16816(sc[n], qlo[kc][0], qlo[kc][1], qlo[kc][2], qlo[kc][3], bh.x, bh.y);
                mma16816(sc[n], qhi[kc][0], qhi[kc][1], qhi[kc][2], qhi[kc][3], bl.x, bl.y);
            }
        }

        // ---- online max (log2 domain), rescale O ----
        float mt0 = -1e30f, mt1 = -1e30f;
#pragma unroll
        for (int n = 0; n < 8; n++) {
            mt0 = fmaxf(mt0, fmaxf(sc[n][0], sc[n][1]));
            mt1 = fmaxf(mt1, fmaxf(sc[n][2], sc[n][3]));
        }
        mt0 = fmaxf(mt0, __shfl_xor_sync(0xffffffffu, mt0, 1));
        mt0 = fmaxf(mt0, __shfl_xor_sync(0xffffffffu, mt0, 2));
        mt1 = fmaxf(mt1, __shfl_xor_sync(0xffffffffu, mt1, 1));
        mt1 = fmaxf(mt1, __shfl_xor_sync(0xffffffffu, mt1, 2));
        float mn0 = fmaxf(m0, mt0), mn1 = fmaxf(m1, mt1);
        float s0 = ex2f(m0 - mn0), s1 = ex2f(m1 - mn1);
        m0 = mn0; m1 = mn1;
#pragma unroll
        for (int nv = 0; nv < 4; nv++) {
            o[nv][0] *= s0; o[nv][1] *= s0;
            o[nv][2] *= s1; o[nv][3] *= s1;
        }

        // ---- P = ex2(S-m) -> A-frags; O += P V (split, 3 passes) ----
#pragma unroll
        for (int kc = 0; kc < 4; kc++) {
            float p00 = ex2f(sc[2 * kc][0] - m0), p01 = ex2f(sc[2 * kc][1] - m0);
            float p02 = ex2f(sc[2 * kc][2] - m1), p03 = ex2f(sc[2 * kc][3] - m1);
            float p10 = ex2f(sc[2 * kc + 1][0] - m0), p11 = ex2f(sc[2 * kc + 1][1] - m0);
            float p12 = ex2f(sc[2 * kc + 1][2] - m1), p13 = ex2f(sc[2 * kc + 1][3] - m1);
            unsigned int a0 = pack2(p01, p00);
            unsigned int a1 = pack2(p03, p02);
            unsigned int a2 = pack2(p11, p10);
            unsigned int a3 = pack2(p13, p12);
            unsigned int a0l = pack2(p01 - unpk_hi(a0), p00 - unpk_lo(a0));
            unsigned int a1l = pack2(p03 - unpk_hi(a1), p02 - unpk_lo(a1));
            unsigned int a2l = pack2(p11 - unpk_hi(a2), p10 - unpk_lo(a2));
            unsigned int a3l = pack2(p13 - unpk_hi(a3), p12 - unpk_lo(a3));
#pragma unroll
            for (int nv = 0; nv < 4; nv++) {
                const char* vrow_h = Vhism[st] + (nv * 8 + lq) * VST_;
                const char* vrow_l = Vlosm[st] + (nv * 8 + lq) * VST_;
                int off = kc * 32 + lr * 8;
                uint2 bh = *(const uint2*)(vrow_h + off);
                uint2 bl = *(const uint2*)(vrow_l + off);
                mma16816(o[nv], a0, a1, a2, a3, bh.x, bh.y);
                mma16816(o[nv], a0l, a1l, a2l, a3l, bh.x, bh.y);
                mma16816(o[nv], a0, a1, a2, a3, bl.x, bl.y);
            }
        }
    }

    // ---- epilogue: cosine(o_row, mhat_row); softmax 1/l cancels in cosine ----
    int trow0 = qbase + wid * 16 + lq;
    int trow1 = trow0 + 8;
    float n20 = 0.f, dt0 = 0.f, n21 = 0.f, dt1 = 0.f;
    const float* mh0 = g_mhat + ((size_t)b * T_ + trow0) * M_;
    const float* mh1 = g_mhat + ((size_t)b * T_ + trow1) * M_;
#pragma unroll
    for (int nv = 0; nv < 4; nv++) {
        int col = nv * 8 + lr * 2;
        float2 w0 = *(const float2*)(mh0 + col);
        float2 w1 = *(const float2*)(mh1 + col);
        n20 += o[nv][0] * o[nv][0] + o[nv][1] * o[nv][1];
        dt0 += o[nv][0] * w0.x + o[nv][1] * w0.y;
        n21 += o[nv][2] * o[nv][2] + o[nv][3] * o[nv][3];
        dt1 += o[nv][2] * w1.x + o[nv][3] * w1.y;
    }
    n20 += __shfl_xor_sync(0xffffffffu, n20, 1);
    dt0 += __shfl_xor_sync(0xffffffffu, dt0, 1);
    n21 += __shfl_xor_sync(0xffffffffu, n21, 1);
    dt1 += __shfl_xor_sync(0xffffffffu, dt1, 1);
    n20 += __shfl_xor_sync(0xffffffffu, n20, 2);
    dt0 += __shfl_xor_sync(0xffffffffu, dt0, 2);
    n21 += __shfl_xor_sync(0xffffffffu, n21, 2);
    dt1 += __shfl_xor_sync(0xffffffffu, dt1, 2);
    if (lr == 0) {
        out[((size_t)b * T_ + trow0) * E_ + e] = dt0 / fmaxf(sqrtf(n20), EPS_);
        out[((size_t)b * T_ + trow1) * E_ + e] = dt1 / fmaxf(sqrtf(n21), EPS_);
    }
}

// ---------------- launch ----------------
extern "C" void kernel_launch(void* const* d_in, const int* in_sizes, int n_in,
                              void* d_out, int out_size) {
    const float* x      = (const float*)d_in[0];
    const float* hidden = (const float*)d_in[1];
    const float* memory = (const float*)d_in[2];
    const float* Wq     = (const float*)d_in[3];
    const float* Wk     = (const float*)d_in[4];
    const float* Wv     = (const float*)d_in[5];
    const float* iq     = (const float*)d_in[6];
    float* out = (float*)d_out;

    // z=0..2: qkv for expert e=z; z=3: mem (g_mhat)
    prep_kernel<<<dim3(T_ / 128, B_, 4), 128>>>(x, memory, iq, hidden, Wq, Wk, Wv);
    attn_kernel<<<dim3(T_ / TQ_, B_, E_), 128>>>(out);
}